// round 2
// baseline (speedup 1.0000x reference)
#include <cuda_runtime.h>
#include <math.h>

// Problem constants
#define BB   4
#define CI   256
#define CO   256
#define HH   64
#define WWD  64
#define HWSZ (HH*WWD)
#define KKT  9

typedef unsigned long long u64;

// ---------------- scratch (device globals; no allocation) ----------------
__device__ float  g_xt[BB*HWSZ*CI];      // x in NHWC   (16.8 MB)
__device__ float  g_wt[KKT*CI*CO];       // weights [k][c][o]  (2.36 MB)
__device__ float  g_wto[KKT*CI*32];      // offset weights [k][c][oc padded 32]
__device__ float4 g_pw[BB*KKT*HWSZ];     // premasked bilinear weights
__device__ int4   g_po[BB*KKT*HWSZ];     // clamped corner element offsets

// ---------------- helpers ----------------
__device__ __forceinline__ void fma2(u64& d, u64 a, u64 b) {
    asm("fma.rn.f32x2 %0, %1, %2, %0;" : "+l"(d) : "l"(a), "l"(b));
}
__device__ __forceinline__ void unpk2(u64 v, float& lo, float& hi) {
    asm("mov.b64 {%0, %1}, %2;" : "=f"(lo), "=f"(hi) : "l"(v));
}
__device__ __forceinline__ void cp16(void* dst, const void* src) {
    unsigned d = (unsigned)__cvta_generic_to_shared(dst);
    asm volatile("cp.async.cg.shared.global [%0], [%1], 16;\n" :: "r"(d), "l"(src));
}
__device__ __forceinline__ void cp_commit() {
    asm volatile("cp.async.commit_group;\n" ::);
}
__device__ __forceinline__ void cp_wait0() {
    asm volatile("cp.async.wait_group 0;\n" ::: "memory");
}

// ---------------- kernel 1: NCHW -> NHWC transpose of x ----------------
__global__ void k_transpose_x(const float* __restrict__ x) {
    __shared__ float tile[32][33];
    int b  = blockIdx.z;
    int c0 = blockIdx.y * 32;
    int p0 = blockIdx.x * 32;
    int tx = threadIdx.x, ty = threadIdx.y;   // 32 x 8
    #pragma unroll
    for (int j = 0; j < 32; j += 8)
        tile[ty + j][tx] = x[((b*CI + c0 + ty + j)*HWSZ) + p0 + tx];
    __syncthreads();
    #pragma unroll
    for (int j = 0; j < 32; j += 8)
        g_xt[(b*HWSZ + p0 + ty + j)*CI + c0 + tx] = tile[tx][ty + j];
}

// ---------------- kernel 2: dcn_w [o][c][k] -> g_wt [k][c][o] ----------------
__global__ void k_transpose_w(const float* __restrict__ dw) {
    int idx = blockIdx.x * 256 + threadIdx.x;
    if (idx < KKT*CI*CO) {
        int k = idx / (CI*CO);
        int r = idx % (CI*CO);
        int c = r / CO;
        int o = r % CO;
        g_wt[idx] = dw[(o*CI + c)*KKT + k];
    }
}

// ---------------- kernel 2b: offset_w [oc][c][k] -> g_wto [k][c][32] ----------------
__global__ void k_transpose_ow(const float* __restrict__ ow) {
    int idx = blockIdx.x * 256 + threadIdx.x;
    if (idx < KKT*CI*32) {
        int k = idx / (CI*32);
        int r = idx % (CI*32);
        int c = r / 32;
        int oc = r % 32;
        g_wto[idx] = (oc < 27) ? ow[(oc*CI + c)*KKT + k] : 0.0f;
    }
}

// ---------------- kernel 3: offset conv + param build ----------------
// grid 256 = (b, h). 128 threads. Mtile=64 pixels, N=32 (27 padded).
__global__ __launch_bounds__(128) void k_offset(const float* __restrict__ ob) {
    __shared__ float sAo[32][136];   // [c][2*pix dup]
    __shared__ float sBo[32][36];    // [c][oc]
    __shared__ float so[64][33];     // conv result

    int tid = threadIdx.x;
    int b = blockIdx.x >> 6;
    int h = blockIdx.x & 63;

    int pg = tid & 15;    // pixel group (4 pixels)
    int og = tid >> 4;    // oc group (4 ocs)

    int p  = tid & 63;    // A-build pixel
    int cq = (tid >> 6) * 16;   // A-build channel base within chunk

    u64 acc[4][2];
    #pragma unroll
    for (int i = 0; i < 4; ++i) { acc[i][0] = 0ULL; acc[i][1] = 0ULL; }

    #pragma unroll 1
    for (int t = 0; t < 9; ++t) {
        int y  = h + t/3 - 1;
        int xx = p + t%3 - 1;
        bool inb = (y >= 0) && (y < HH) && (xx >= 0) && (xx < WWD);
        const float* xrow = g_xt + ((size_t)(b*HWSZ) + (size_t)(y*WWD + xx)) * CI;

        #pragma unroll 1
        for (int cc = 0; cc < 8; ++cc) {
            int c0 = cc * 32;
            // A build: float4 coalesced from NHWC, store duplicated
            #pragma unroll
            for (int qq = 0; qq < 4; ++qq) {
                int c4 = cq + qq*4;
                float4 f = make_float4(0.f, 0.f, 0.f, 0.f);
                if (inb) f = *(const float4*)(xrow + c0 + c4);
                *(float2*)&sAo[c4+0][2*p] = make_float2(f.x, f.x);
                *(float2*)&sAo[c4+1][2*p] = make_float2(f.y, f.y);
                *(float2*)&sAo[c4+2][2*p] = make_float2(f.z, f.z);
                *(float2*)&sAo[c4+3][2*p] = make_float2(f.w, f.w);
            }
            // B build: coalesced from g_wto
            #pragma unroll
            for (int q = 0; q < 8; ++q) {
                int idx = tid + q*128;
                int cl = idx >> 5, oc = idx & 31;
                sBo[cl][oc] = g_wto[(t*CI + c0 + cl)*32 + oc];
            }
            __syncthreads();
            #pragma unroll
            for (int cl = 0; cl < 32; ++cl) {
                ulonglong2 a01 = *(const ulonglong2*)&sAo[cl][8*pg];
                ulonglong2 a23 = *(const ulonglong2*)&sAo[cl][8*pg + 4];
                ulonglong2 bb  = *(const ulonglong2*)&sBo[cl][4*og];
                fma2(acc[0][0], a01.x, bb.x); fma2(acc[0][1], a01.x, bb.y);
                fma2(acc[1][0], a01.y, bb.x); fma2(acc[1][1], a01.y, bb.y);
                fma2(acc[2][0], a23.x, bb.x); fma2(acc[2][1], a23.x, bb.y);
                fma2(acc[3][0], a23.y, bb.x); fma2(acc[3][1], a23.y, bb.y);
            }
            __syncthreads();
        }
    }

    // scatter conv results
    #pragma unroll
    for (int i = 0; i < 4; ++i) {
        float lo, hi;
        unpk2(acc[i][0], lo, hi);
        so[4*pg + i][4*og + 0] = lo; so[4*pg + i][4*og + 1] = hi;
        unpk2(acc[i][1], lo, hi);
        so[4*pg + i][4*og + 2] = lo; so[4*pg + i][4*og + 3] = hi;
    }
    __syncthreads();

    if (tid < 64) {
        float ov[27];
        #pragma unroll
        for (int oc = 0; oc < 27; ++oc) ov[oc] = so[tid][oc] + ob[oc];

        int w  = tid;
        int hw = h * WWD + w;
        #pragma unroll
        for (int kk = 0; kk < 9; ++kk) {
            float dy = ov[2*kk];
            float dx = ov[2*kk + 1];
            float m  = 1.0f / (1.0f + expf(-ov[18 + kk]));
            int ki = kk / 3, kj = kk % 3;
            float py = (float)(h - 1 + ki) + dy;
            float px = (float)(w - 1 + kj) + dx;
            float fy = floorf(py), fx = floorf(px);
            float wy = py - fy,    wx = px - fx;
            int y0 = (int)fy, x0 = (int)fx;
            int y1 = y0 + 1,  x1 = x0 + 1;

            bool vy0 = (y0 >= 0) && (y0 < HH);
            bool vy1 = (y1 >= 0) && (y1 < HH);
            bool vx0 = (x0 >= 0) && (x0 < WWD);
            bool vx1 = (x1 >= 0) && (x1 < WWD);

            float w00 = (1.0f - wy) * (1.0f - wx) * m * ((vy0 && vx0) ? 1.0f : 0.0f);
            float w01 = (1.0f - wy) * wx          * m * ((vy0 && vx1) ? 1.0f : 0.0f);
            float w10 = wy * (1.0f - wx)          * m * ((vy1 && vx0) ? 1.0f : 0.0f);
            float w11 = wy * wx                   * m * ((vy1 && vx1) ? 1.0f : 0.0f);

            int yc0 = min(max(y0, 0), HH - 1);
            int yc1 = min(max(y1, 0), HH - 1);
            int xc0 = min(max(x0, 0), WWD - 1);
            int xc1 = min(max(x1, 0), WWD - 1);

            int idx = ((b*KKT + kk)*HWSZ) + hw;
            g_pw[idx] = make_float4(w00, w01, w10, w11);
            g_po[idx] = make_int4((yc0*WWD + xc0)*CI, (yc0*WWD + xc1)*CI,
                                  (yc1*WWD + xc0)*CI, (yc1*WWD + xc1)*CI);
        }
    }
}

// ---------------- kernel 4: fused bilinear-sample + main GEMM (pipelined) ----------------
struct __align__(16) SmemMain {
    float  sA[2][64][68];     // duplicated A: [buf][pix][2c+{0,1}]
    float  sB[2][32][260];    // [buf][c][o]
    float4 sPw[2][64];        // param ring (tap parity)
    int4   sPo[2][64];
};

#define GATHER(chunk) do { \
    int _t = (chunk) >> 3; int _c0 = ((chunk) & 7) * 32; \
    _Pragma("unroll") \
    for (int _r = 0; _r < 2; ++_r) { \
        int _pix = prow + 32*_r; \
        int4 _po = S.sPo[_t & 1][_pix]; \
        const float* _base = xb + _c0 + clo; \
        v[_r][0] = *(const float4*)(_base + _po.x); \
        v[_r][1] = *(const float4*)(_base + _po.y); \
        v[_r][2] = *(const float4*)(_base + _po.z); \
        v[_r][3] = *(const float4*)(_base + _po.w); \
    } } while (0)

#define BLEND(chunk, bufw) do { \
    int _t = (chunk) >> 3; \
    _Pragma("unroll") \
    for (int _r = 0; _r < 2; ++_r) { \
        int _pix = prow + 32*_r; \
        float4 _wv = S.sPw[_t & 1][_pix]; \
        float _sx = _wv.x*v[_r][0].x + _wv.y*v[_r][1].x + _wv.z*v[_r][2].x + _wv.w*v[_r][3].x; \
        float _sy = _wv.x*v[_r][0].y + _wv.y*v[_r][1].y + _wv.z*v[_r][2].y + _wv.w*v[_r][3].y; \
        float _sz = _wv.x*v[_r][0].z + _wv.y*v[_r][1].z + _wv.z*v[_r][2].z + _wv.w*v[_r][3].z; \
        float _sw = _wv.x*v[_r][0].w + _wv.y*v[_r][1].w + _wv.z*v[_r][2].w + _wv.w*v[_r][3].w; \
        *(float4*)&S.sA[bufw][_pix][2*clo]     = make_float4(_sx, _sx, _sy, _sy); \
        *(float4*)&S.sA[bufw][_pix][2*clo + 4] = make_float4(_sz, _sz, _sw, _sw); \
    } } while (0)

#define LOADB(chunk, bufw) do { \
    int _t = (chunk) >> 3; int _c0 = ((chunk) & 7) * 32; \
    const float* _src = g_wt + ((_t*CI + _c0 + brow)*CO) + bcol; \
    float* _dst = &S.sB[bufw][brow][bcol]; \
    _Pragma("unroll") \
    for (int _q = 0; _q < 8; ++_q) cp16(_dst + _q*32, _src + _q*32); \
    cp_commit(); } while (0)

__global__ __launch_bounds__(256, 2) void k_main(float* __restrict__ out) {
    extern __shared__ char smem_raw[];
    SmemMain& S = *reinterpret_cast<SmemMain*>(smem_raw);

    int tid = threadIdx.x;
    int bid = blockIdx.x;
    int b = bid >> 6;
    int h = bid & 63;
    int hw0 = h * WWD;
    const float* xb = g_xt + (size_t)b * HWSZ * CI;

    int mt8 = (tid >> 5) * 8;     // 8 pixels per thread
    int nt4 = (tid & 31) * 4;     // 4+4 output cols
    int clo = (tid & 7) * 4;      // A-build channel offset (float4)
    int prow = tid >> 3;          // A-build pixel (x2)
    int brow = tid >> 3;          // B-load row
    int bcol = (tid & 7) * 4;     // B-load col base

    u64 acc[8][4];
    #pragma unroll
    for (int i = 0; i < 8; ++i)
        #pragma unroll
        for (int j = 0; j < 4; ++j) acc[i][j] = 0ULL;

    // preload params for taps 0 and 1
    if (tid < 128) {
        int t = tid >> 6;
        int pp = tid & 63;
        int pidx = ((b*KKT + t)*HWSZ) + hw0 + pp;
        S.sPw[t][pp] = g_pw[pidx];
        S.sPo[t][pp] = g_po[pidx];
    }
    __syncthreads();

    float4 v[2][4];

    // prologue: chunk 0
    GATHER(0);
    LOADB(0, 0);
    BLEND(0, 0);
    cp_wait0();
    __syncthreads();

    #pragma unroll 1
    for (int i = 0; i < 72; ++i) {
        int buf = i & 1;

        // param ring prefetch: tap (i>>3)+1, one tap ahead of its first use
        if (i >= 8 && i <= 56 && (i & 7) == 0) {
            int t = (i >> 3) + 1;
            if (tid < 64) {
                int pidx = ((b*KKT + t)*HWSZ) + hw0 + tid;
                S.sPw[t & 1][tid] = g_pw[pidx];
                S.sPo[t & 1][tid] = g_po[pidx];
            }
        }

        // prefetch next chunk (A gathers into regs, B via cp.async into other buf)
        if (i < 71) {
            GATHER(i + 1);
            LOADB(i + 1, buf ^ 1);
        }

        // GEMM over current chunk: 16 x (2 channels)
        {
            const float (*A)[68]  = S.sA[buf];
            const float (*Bm)[260] = S.sB[buf];
            #pragma unroll
            for (int c2 = 0; c2 < 16; ++c2) {
                ulonglong2 b00 = *(const ulonglong2*)&Bm[2*c2    ][nt4];
                ulonglong2 b01 = *(const ulonglong2*)&Bm[2*c2    ][nt4 + 128];
                ulonglong2 b10 = *(const ulonglong2*)&Bm[2*c2 + 1][nt4];
                ulonglong2 b11 = *(const ulonglong2*)&Bm[2*c2 + 1][nt4 + 128];
                #pragma unroll
                for (int i8 = 0; i8 < 8; ++i8) {
                    ulonglong2 a = *(const ulonglong2*)&A[mt8 + i8][4*c2];
                    fma2(acc[i8][0], a.x, b00.x); fma2(acc[i8][1], a.x, b00.y);
                    fma2(acc[i8][2], a.x, b01.x); fma2(acc[i8][3], a.x, b01.y);
                    fma2(acc[i8][0], a.y, b10.x); fma2(acc[i8][1], a.y, b10.y);
                    fma2(acc[i8][2], a.y, b11.x); fma2(acc[i8][3], a.y, b11.y);
                }
            }
        }

        // blend prefetched A into other buf, wait for B
        if (i < 71) {
            BLEND(i + 1, buf ^ 1);
            cp_wait0();
        }
        __syncthreads();
    }

    // epilogue: out[b][n][h][w]
    int obase = (b*CO)*HWSZ + hw0;
    #pragma unroll
    for (int i8 = 0; i8 < 8; ++i8) {
        int pix = mt8 + i8;
        #pragma unroll
        for (int j = 0; j < 4; ++j) {
            float lo, hi;
            unpk2(acc[i8][j], lo, hi);
            int n = (j & 1)*2 + (j >> 1)*128 + nt4;
            out[obase + n*HWSZ + pix]       = lo;
            out[obase + (n + 1)*HWSZ + pix] = hi;
        }
    }
}

// ---------------- launch ----------------
extern "C" void kernel_launch(void* const* d_in, const int* in_sizes, int n_in,
                              void* d_out, int out_size) {
    (void)in_sizes; (void)n_in; (void)out_size;
    const float* x  = (const float*)d_in[0];   // (4,256,64,64)
    const float* ow = (const float*)d_in[1];   // (27,256,3,3)
    const float* ob = (const float*)d_in[2];   // (27,)
    const float* dw = (const float*)d_in[3];   // (256,256,3,3)
    float* out = (float*)d_out;                // (4,256,64,64)

    cudaFuncSetAttribute(k_main, cudaFuncAttributeMaxDynamicSharedMemorySize,
                         (int)sizeof(SmemMain));

    dim3 tb(32, 8);
    dim3 tg(HWSZ/32, CI/32, BB);
    k_transpose_x<<<tg, tb>>>(x);
    k_transpose_w<<<(KKT*CI*CO + 255)/256, 256>>>(dw);
    k_transpose_ow<<<(KKT*CI*32 + 255)/256, 256>>>(ow);
    k_offset<<<256, 128>>>(ob);
    k_main<<<256, 256, sizeof(SmemMain)>>>(out);
}